// round 11
// baseline (speedup 1.0000x reference)
#include <cuda_runtime.h>
#include <math_constants.h>

// Problem constants (NB, LQ, LK, DK, DV = 16, 384, 384, 64, 64)
#define NB 16
#define LQ 384
#define LK 384
#define DK 64
#define DV 64
#define INV_TEMP 0.125f  // 1 / TEMPERATURE, TEMPERATURE = 8.0
#define RPB 6            // rows per block: 6144/6 = 1024 blocks = single wave

// Scratch for attn probabilities in case the harness output only holds `output`.
__device__ float g_attn_scratch[NB * LQ * LK];

// ---------------------------------------------------------------------------
// Block softmax over buf[0..383] (256 threads). Writes normalized probs back
// to buf and to arow (gmem, coalesced). Identical math to the R8 phase B.
// ---------------------------------------------------------------------------
__device__ __forceinline__ void block_softmax(float* buf, float* arow,
                                              float* red,
                                              int tid, int lane, int warp)
{
    const float v1 = buf[tid];
    const float v2 = (tid < LK - 256) ? buf[tid + 256] : -CUDART_INF_F;

    // Block max.
    float m = fmaxf(v1, v2);
#pragma unroll
    for (int s = 16; s > 0; s >>= 1)
        m = fmaxf(m, __shfl_xor_sync(0xFFFFFFFFu, m, s));
    if (lane == 0) red[warp] = m;
    __syncthreads();
    if (tid < 32) {
        float t = (lane < 8) ? red[lane] : -CUDART_INF_F;
#pragma unroll
        for (int s = 4; s > 0; s >>= 1)
            t = fmaxf(t, __shfl_xor_sync(0xFFFFFFFFu, t, s));
        if (lane == 0) red[0] = t;
    }
    __syncthreads();
    const float mm = red[0];

    // exp + block sum.
    const float e1 = __expf(v1 - mm);
    const float e2 = (tid < LK - 256) ? __expf(v2 - mm) : 0.0f;
    float s = e1 + e2;
#pragma unroll
    for (int sh = 16; sh > 0; sh >>= 1)
        s += __shfl_xor_sync(0xFFFFFFFFu, s, sh);
    if (lane == 0) red[8 + warp] = s;
    __syncthreads();
    if (tid < 32) {
        float t = (lane < 8) ? red[8 + lane] : 0.0f;
#pragma unroll
        for (int sh = 4; sh > 0; sh >>= 1)
            t += __shfl_xor_sync(0xFFFFFFFFu, t, sh);
        if (lane == 0) red[8] = t;
    }
    __syncthreads();
    const float inv = 1.0f / red[8];

    const float p1 = e1 * inv;
    buf[tid]  = p1;
    arow[tid] = p1;
    if (tid < LK - 256) {
        const float p2 = e2 * inv;
        buf[tid + 256]  = p2;
        arow[tid + 256] = p2;
    }
}

// ---------------------------------------------------------------------------
// Fused pipelined kernel. 1024 blocks x 256 threads, 6 rows per block,
// single occupancy wave (capacity 148x7 = 1036 >= 1024): no wave-lockstep.
//
// Per row: phase A (q.K dots, half-warp per K-row, 512B-coalesced, L2-served)
// for row r+1 is INTERLEAVED into phase C (rel_pos_v DRAM stream) of row r —
// both index the same k per iteration, so it is one fused 24-iter loop.
// DRAM idles only during the one initial A(0)+B(0) prologue and the 6 short
// softmax slivers, instead of once per wave (R8: 5.2 waves x ~2.5us = 13us).
// smem ~9.7KB keeps the L1 carveout large (R9 lesson: big smem evicted K
// from L1 and cost 23us).
// ---------------------------------------------------------------------------
__global__ __launch_bounds__(256, 7)
void fused_kernel(const float* __restrict__ q,
                  const float* __restrict__ k,
                  const float* __restrict__ rpv,
                  float* __restrict__ out,
                  float* __restrict__ attn_ext)
{
    __shared__ float4 sq4[RPB][DK / 4];  // 6 q rows, 1.5 KB
    __shared__ float  sab[2][LK];        // double-buffered scores/probs, 3 KB
    __shared__ float4 rbuf[256];         // reduction buffer, 4 KB
    __shared__ float  red[16];           // softmax partials

    float* attn = attn_ext ? attn_ext : g_attn_scratch;

    const int nq0  = blockIdx.x * RPB;   // first row of this block
    const int n    = nq0 / LQ;           // 64 blocks per batch: same n for all 6
    const int tid  = threadIdx.x;
    const int lane = tid & 31;
    const int warp = tid >> 5;
    const int d4   = tid & 15;           // float4 column (both K-dot and stream)
    const int kk   = tid >> 4;           // k-row / k-slice id (both phases)

    const float4* kbase = reinterpret_cast<const float4*>(
        k + (size_t)n * LK * DK);

    // Stage the 6 q rows (96 float4, coalesced).
    if (tid < RPB * (DK / 4)) {
        reinterpret_cast<float4*>(sq4)[tid] =
            reinterpret_cast<const float4*>(q + (size_t)nq0 * DK)[tid];
    }
    __syncthreads();

    // ---- Prologue: phase A + B for row 0 (only unoverlapped region). ----
    {
        const float4 qv = sq4[0][d4];
#pragma unroll
        for (int i = 0; i < LK / 16; i++) {
            const int krow = kk + 16 * i;
            const float4 kv = kbase[krow * (DK / 4) + d4];
            float p = qv.x * kv.x + qv.y * kv.y + qv.z * kv.z + qv.w * kv.w;
            p += __shfl_xor_sync(0xFFFFFFFFu, p, 8);
            p += __shfl_xor_sync(0xFFFFFFFFu, p, 4);
            p += __shfl_xor_sync(0xFFFFFFFFu, p, 2);
            p += __shfl_xor_sync(0xFFFFFFFFu, p, 1);
            if (d4 == 0) sab[0][krow] = p * INV_TEMP;
        }
    }
    __syncthreads();
    block_softmax(sab[0], attn + (size_t)nq0 * LK, red, tid, lane, warp);
    __syncthreads();

    // ---- Main pipeline over the 6 rows. ----
#pragma unroll 1
    for (int r = 0; r < RPB; r++) {
        float* cur = sab[r & 1];         // probs of row r
        float* nxt = sab[(r + 1) & 1];   // scores of row r+1 (written below)
        const float4* base = reinterpret_cast<const float4*>(
            rpv + (size_t)(nq0 + r) * LK * DV);

        float4 acc = make_float4(0.f, 0.f, 0.f, 0.f);

        if (r < RPB - 1) {
            // Phase C (row r) interleaved with phase A (row r+1).
            const float4 qv = sq4[r + 1][d4];
#pragma unroll
            for (int i = 0; i < LK / 16; i++) {
                const int kidx = kk + 16 * i;
                // C: DRAM stream + prob FMA.
                const float  a = cur[kidx];
                const float4 v = base[kidx * (DV / 4) + d4];
                acc.x += a * v.x;
                acc.y += a * v.y;
                acc.z += a * v.z;
                acc.w += a * v.w;
                // A: K-dot for row r+1 (same k index, L2/L1-served).
                const float4 kv = kbase[kidx * (DK / 4) + d4];
                float p = qv.x * kv.x + qv.y * kv.y + qv.z * kv.z + qv.w * kv.w;
                p += __shfl_xor_sync(0xFFFFFFFFu, p, 8);
                p += __shfl_xor_sync(0xFFFFFFFFu, p, 4);
                p += __shfl_xor_sync(0xFFFFFFFFu, p, 2);
                p += __shfl_xor_sync(0xFFFFFFFFu, p, 1);
                if (d4 == 0) nxt[kidx] = p * INV_TEMP;
            }
        } else {
            // Last row: pure phase C.
#pragma unroll
            for (int i = 0; i < LK / 16; i++) {
                const int kidx = kk + 16 * i;
                const float  a = cur[kidx];
                const float4 v = base[kidx * (DV / 4) + d4];
                acc.x += a * v.x;
                acc.y += a * v.y;
                acc.z += a * v.z;
                acc.w += a * v.w;
            }
        }

        // Block reduction of the 16 k-slices -> out row nq0+r.
        rbuf[tid] = acc;
        __syncthreads();
#pragma unroll
        for (int s = 128; s >= 16; s >>= 1) {
            if (tid < s) {
                float4 a = rbuf[tid];
                float4 b = rbuf[tid + s];
                a.x += b.x; a.y += b.y; a.z += b.z; a.w += b.w;
                rbuf[tid] = a;
            }
            __syncthreads();
        }
        if (tid < DV) {
            out[(size_t)(nq0 + r) * DV + tid] =
                reinterpret_cast<const float*>(rbuf)[tid];
        }
        __syncthreads();   // rbuf reuse + nxt scores complete

        // Phase B for row r+1 (short DRAM-idle sliver).
        if (r < RPB - 1) {
            block_softmax(nxt, attn + (size_t)(nq0 + r + 1) * LK,
                          red, tid, lane, warp);
            __syncthreads();
        }
    }
}

// ---------------------------------------------------------------------------
// Launch. Inputs (metadata order) = q, k, v, rel_pos, rel_pos_v.
// v and rel_pos are unused by the reference — never touched.
// Output layout: [output (NB*LQ*DV) | attn (NB*LQ*LK)] when out_size covers
// both (branch taken and passing since R3); otherwise attn -> scratch.
// ---------------------------------------------------------------------------
extern "C" void kernel_launch(void* const* d_in, const int* in_sizes, int n_in,
                              void* d_out, int out_size)
{
    const float* q   = (const float*)d_in[0];
    const float* k   = (const float*)d_in[1];
    const float* rpv = (const float*)d_in[4];
    float* out = (float*)d_out;

    const long long out_elems  = (long long)NB * LQ * DV;   // 393216
    const long long attn_elems = (long long)NB * LQ * LK;   // 2359296

    float* attn_ext = nullptr;  // null -> kernel falls back to g_attn_scratch
    if ((long long)out_size >= out_elems + attn_elems) {
        attn_ext = out + out_elems;
    }

    fused_kernel<<<(NB * LQ) / RPB, 256>>>(q, k, rpv, out, attn_ext);
}

// round 12
// speedup vs baseline: 1.1655x; 1.1655x over previous
#include <cuda_runtime.h>
#include <math_constants.h>

// Problem constants (NB, LQ, LK, DK, DV = 16, 384, 384, 64, 64)
#define NB 16
#define LQ 384
#define LK 384
#define DK 64
#define DV 64
#define INV_TEMP 0.125f  // 1 / TEMPERATURE, TEMPERATURE = 8.0
#define RPB 6            // rows per block: 6144/6 = 1024 blocks = single wave

// Scratch for attn probabilities in case the harness output only holds `output`.
__device__ float g_attn_scratch[NB * LQ * LK];

// ---------------------------------------------------------------------------
// Block softmax over buf[0..383] (256 threads). Writes normalized probs back
// to buf and to arow (gmem, streaming stores). Same math as R8/R10 (passed).
// ---------------------------------------------------------------------------
__device__ __forceinline__ void block_softmax(float* buf, float* arow,
                                              float* red,
                                              int tid, int lane, int warp)
{
    const float v1 = buf[tid];
    const float v2 = (tid < LK - 256) ? buf[tid + 256] : -CUDART_INF_F;

    // Block max.
    float m = fmaxf(v1, v2);
#pragma unroll
    for (int s = 16; s > 0; s >>= 1)
        m = fmaxf(m, __shfl_xor_sync(0xFFFFFFFFu, m, s));
    if (lane == 0) red[warp] = m;
    __syncthreads();
    if (tid < 32) {
        float t = (lane < 8) ? red[lane] : -CUDART_INF_F;
#pragma unroll
        for (int s = 4; s > 0; s >>= 1)
            t = fmaxf(t, __shfl_xor_sync(0xFFFFFFFFu, t, s));
        if (lane == 0) red[0] = t;
    }
    __syncthreads();
    const float mm = red[0];

    // exp + block sum.
    const float e1 = __expf(v1 - mm);
    const float e2 = (tid < LK - 256) ? __expf(v2 - mm) : 0.0f;
    float s = e1 + e2;
#pragma unroll
    for (int sh = 16; sh > 0; sh >>= 1)
        s += __shfl_xor_sync(0xFFFFFFFFu, s, sh);
    if (lane == 0) red[8 + warp] = s;
    __syncthreads();
    if (tid < 32) {
        float t = (lane < 8) ? red[8 + lane] : 0.0f;
#pragma unroll
        for (int sh = 4; sh > 0; sh >>= 1)
            t += __shfl_xor_sync(0xFFFFFFFFu, t, sh);
        if (lane == 0) red[8] = t;
    }
    __syncthreads();
    const float inv = 1.0f / red[8];

    const float p1 = e1 * inv;
    buf[tid] = p1;
    __stcs(arow + tid, p1);                 // streaming store: don't cache
    if (tid < LK - 256) {
        const float p2 = e2 * inv;
        buf[tid + 256] = p2;
        __stcs(arow + tid + 256, p2);
    }
}

// ---------------------------------------------------------------------------
// Fused pipelined kernel (R10 structure — its ONLY failure was cache policy).
// 1024 blocks x 256 threads, 6 rows per block, single wave (148x7=1036).
//
// R10 post-mortem: DRAM traffic doubled (1.26 GB) because the rpv stream
// turned over all of L2 every ~20us, evicting K between the interleaved
// re-reads -> 576 MB of K went to DRAM. Fix (this round): rpv is loaded with
// __ldcs (evict-first in L1 AND L2) and outputs stored with __stcs, so the
// streaming data never competes with K for cache. K loads stay default ->
// K[n] (96 KB/batch, shared by the ~7 co-resident same-batch blocks) lives
// in the ~160 KB L1 carveout + L2, exactly the R8-measured behavior, now
// maintained *while* streaming. The K-dots for row r+1 then ride free in
// the latency shadow of row r's DRAM stream (issue was only 24.7%).
// ---------------------------------------------------------------------------
__global__ __launch_bounds__(256, 7)
void fused_kernel(const float* __restrict__ q,
                  const float* __restrict__ k,
                  const float* __restrict__ rpv,
                  float* __restrict__ out,
                  float* __restrict__ attn_ext)
{
    __shared__ float4 sq4[RPB][DK / 4];  // 6 q rows, 1.5 KB
    __shared__ float  sab[2][LK];        // double-buffered scores/probs, 3 KB
    __shared__ float4 rbuf[256];         // reduction buffer, 4 KB
    __shared__ float  red[16];           // softmax partials

    float* attn = attn_ext ? attn_ext : g_attn_scratch;

    const int nq0  = blockIdx.x * RPB;   // first row of this block
    const int n    = nq0 / LQ;           // 64 blocks per batch: same n for all 6
    const int tid  = threadIdx.x;
    const int lane = tid & 31;
    const int warp = tid >> 5;
    const int d4   = tid & 15;           // float4 column (both K-dot and stream)
    const int kk   = tid >> 4;           // k-row / k-slice id (both phases)

    const float4* kbase = reinterpret_cast<const float4*>(
        k + (size_t)n * LK * DK);

    // Stage the 6 q rows (96 float4, coalesced).
    if (tid < RPB * (DK / 4)) {
        reinterpret_cast<float4*>(sq4)[tid] =
            reinterpret_cast<const float4*>(q + (size_t)nq0 * DK)[tid];
    }
    __syncthreads();

    // ---- Prologue: phase A + B for row 0 (only unoverlapped region). ----
    {
        const float4 qv = sq4[0][d4];
#pragma unroll
        for (int i = 0; i < LK / 16; i++) {
            const int krow = kk + 16 * i;
            const float4 kv = kbase[krow * (DK / 4) + d4];   // default: cacheable
            float p = qv.x * kv.x + qv.y * kv.y + qv.z * kv.z + qv.w * kv.w;
            p += __shfl_xor_sync(0xFFFFFFFFu, p, 8);
            p += __shfl_xor_sync(0xFFFFFFFFu, p, 4);
            p += __shfl_xor_sync(0xFFFFFFFFu, p, 2);
            p += __shfl_xor_sync(0xFFFFFFFFu, p, 1);
            if (d4 == 0) sab[0][krow] = p * INV_TEMP;
        }
    }
    __syncthreads();
    block_softmax(sab[0], attn + (size_t)nq0 * LK, red, tid, lane, warp);
    __syncthreads();

    // ---- Main pipeline over the 6 rows. ----
#pragma unroll 1
    for (int r = 0; r < RPB; r++) {
        float* cur = sab[r & 1];         // probs of row r
        float* nxt = sab[(r + 1) & 1];   // scores of row r+1 (written below)
        const float4* base = reinterpret_cast<const float4*>(
            rpv + (size_t)(nq0 + r) * LK * DV);

        float4 acc = make_float4(0.f, 0.f, 0.f, 0.f);

        if (r < RPB - 1) {
            // Phase C (row r, streaming loads) interleaved with phase A (row r+1).
            const float4 qv = sq4[r + 1][d4];
#pragma unroll
            for (int i = 0; i < LK / 16; i++) {
                const int kidx = kk + 16 * i;
                // C: DRAM stream, evict-first so it never thrashes K's cache.
                const float  a = cur[kidx];
                const float4 v = __ldcs(&base[kidx * (DV / 4) + d4]);
                acc.x += a * v.x;
                acc.y += a * v.y;
                acc.z += a * v.z;
                acc.w += a * v.w;
                // A: K-dot for row r+1 (same k index, L1/L2-served).
                const float4 kv = kbase[kidx * (DK / 4) + d4];
                float p = qv.x * kv.x + qv.y * kv.y + qv.z * kv.z + qv.w * kv.w;
                p += __shfl_xor_sync(0xFFFFFFFFu, p, 8);
                p += __shfl_xor_sync(0xFFFFFFFFu, p, 4);
                p += __shfl_xor_sync(0xFFFFFFFFu, p, 2);
                p += __shfl_xor_sync(0xFFFFFFFFu, p, 1);
                if (d4 == 0) nxt[kidx] = p * INV_TEMP;
            }
        } else {
            // Last row: pure phase C.
#pragma unroll
            for (int i = 0; i < LK / 16; i++) {
                const int kidx = kk + 16 * i;
                const float  a = cur[kidx];
                const float4 v = __ldcs(&base[kidx * (DV / 4) + d4]);
                acc.x += a * v.x;
                acc.y += a * v.y;
                acc.z += a * v.z;
                acc.w += a * v.w;
            }
        }

        // Block reduction of the 16 k-slices -> out row nq0+r.
        rbuf[tid] = acc;
        __syncthreads();
#pragma unroll
        for (int s = 128; s >= 16; s >>= 1) {
            if (tid < s) {
                float4 a = rbuf[tid];
                float4 b = rbuf[tid + s];
                a.x += b.x; a.y += b.y; a.z += b.z; a.w += b.w;
                rbuf[tid] = a;
            }
            __syncthreads();
        }
        if (tid < DV) {
            __stcs(out + (size_t)(nq0 + r) * DV + tid,
                   reinterpret_cast<const float*>(rbuf)[tid]);
        }
        __syncthreads();   // rbuf reuse + nxt scores complete

        // Phase B for row r+1 (short sliver).
        if (r < RPB - 1) {
            block_softmax(nxt, attn + (size_t)(nq0 + r + 1) * LK,
                          red, tid, lane, warp);
            __syncthreads();
        }
    }
}

// ---------------------------------------------------------------------------
// Launch. Inputs (metadata order) = q, k, v, rel_pos, rel_pos_v.
// v and rel_pos are unused by the reference — never touched.
// Output layout: [output (NB*LQ*DV) | attn (NB*LQ*LK)] when out_size covers
// both (branch taken and passing since R3); otherwise attn -> scratch.
// ---------------------------------------------------------------------------
extern "C" void kernel_launch(void* const* d_in, const int* in_sizes, int n_in,
                              void* d_out, int out_size)
{
    const float* q   = (const float*)d_in[0];
    const float* k   = (const float*)d_in[1];
    const float* rpv = (const float*)d_in[4];
    float* out = (float*)d_out;

    const long long out_elems  = (long long)NB * LQ * DV;   // 393216
    const long long attn_elems = (long long)NB * LQ * LK;   // 2359296

    float* attn_ext = nullptr;  // null -> kernel falls back to g_attn_scratch
    if ((long long)out_size >= out_elems + attn_elems) {
        attn_ext = out + out_elems;
    }

    fused_kernel<<<(NB * LQ) / RPB, 256>>>(q, k, rpv, out, attn_ext);
}

// round 13
// speedup vs baseline: 2.2641x; 1.9426x over previous
#include <cuda_runtime.h>
#include <math_constants.h>

// Problem constants (NB, LQ, LK, DK, DV = 16, 384, 384, 64, 64)
#define NB 16
#define LQ 384
#define LK 384
#define DK 64
#define DV 64
#define INV_TEMP 0.125f  // 1 / TEMPERATURE, TEMPERATURE = 8.0

// Scratch for attn probabilities in case the harness output only holds `output`.
__device__ float g_attn_scratch[NB * LQ * LK];

// ---------------------------------------------------------------------------
// Single-loop fused kernel. Grid = 6144 (one block per (n,q)) x 256 threads —
// the R8 grid whose measured DRAM traffic was ~ideal (629 MB): with one-row
// blocks, every K line is re-touched by some same-batch block at sub-us
// spacing, so K stays L2-warm with NO phase burst and NO cache hints needed.
// (R10/R11 failed because 6-row blocks re-touched K every ~32us > the ~22us
// L2 turnover window; __ldcs could not save it.)
//
// Per iteration i (k-row kidx = (tid>>4) + 16*i):
//   - half-warp cooperative K-dot: lane d4 loads K[kidx][d4], 4 xor-shfls
//     broadcast the full score s to all 16 lanes;
//   - ONLINE softmax update (flash-attention style): m,Z,acc rescale + FMA
//     of v = rpv[kidx][d4] (evict-first streaming load).
// So rel_pos_v loads start at instruction 1 and never pause for a softmax
// phase: the per-wave serial prologue that cost R8 its 13us is gone.
// Raw scores are parked in smem; epilogue recomputes attn = e^{s-m}/Z.
// Block reduction merges (m, Z, acc) triples with rescaling.
// ---------------------------------------------------------------------------
__global__ __launch_bounds__(256, 6)
void fused_kernel(const float* __restrict__ q,
                  const float* __restrict__ k,
                  const float* __restrict__ rpv,
                  float* __restrict__ out,
                  float* __restrict__ attn_ext)
{
    __shared__ float4 sq4[DK / 4];   // q row, 256 B
    __shared__ float  sa[LK];        // raw scores (already * INV_TEMP), 1.5 KB
    __shared__ float4 rbuf[256];     // acc reduction, 4 KB
    __shared__ float  rm[256];       // running-max reduction, 1 KB
    __shared__ float  rz[256];       // running-sum reduction, 1 KB
    __shared__ float  red[2];        // broadcast (m_final, 1/Z_final)

    float* attn = attn_ext ? attn_ext : g_attn_scratch;

    const int nq  = blockIdx.x;            // n*LQ + q
    const int n   = nq / LQ;
    const int tid = threadIdx.x;
    const int d4  = tid & 15;              // float4 column (K-dot AND stream)
    const int kk  = tid >> 4;              // half-warp id == k-slice start

    if (tid < DK / 4) {
        sq4[tid] = reinterpret_cast<const float4*>(q + (size_t)nq * DK)[tid];
    }
    __syncthreads();
    const float4 qv = sq4[d4];

    const float4* kb   = reinterpret_cast<const float4*>(
        k + (size_t)n * LK * DK);
    const float4* base = reinterpret_cast<const float4*>(
        rpv + (size_t)nq * LK * DV);

    float4 acc = make_float4(0.f, 0.f, 0.f, 0.f);
    float  m   = -CUDART_INF_F;
    float  Z   = 0.f;

#pragma unroll 4
    for (int i = 0; i < LK / 16; i++) {          // 24 iterations
        const int kidx = kk + 16 * i;

        // Streaming value load (DRAM) — issued immediately, evict-first.
        const float4 v = __ldcs(&base[kidx * (DV / 4) + d4]);
        // K load (L2-warm by the continuous-touch argument).
        const float4 kv = kb[kidx * (DK / 4) + d4];

        // Cooperative dot: fold 16 lanes, result in all lanes.
        float s = qv.x * kv.x + qv.y * kv.y + qv.z * kv.z + qv.w * kv.w;
        s += __shfl_xor_sync(0xFFFFFFFFu, s, 1);
        s += __shfl_xor_sync(0xFFFFFFFFu, s, 2);
        s += __shfl_xor_sync(0xFFFFFFFFu, s, 4);
        s += __shfl_xor_sync(0xFFFFFFFFu, s, 8);
        s *= INV_TEMP;
        if (d4 == 0) sa[kidx] = s;               // park raw score for epilogue

        // Online softmax update. First iter: m=-inf -> sc=0, es=1: exact.
        const float mn = fmaxf(m, s);
        const float sc = __expf(m - mn);
        const float es = __expf(s - mn);
        acc.x = acc.x * sc + es * v.x;
        acc.y = acc.y * sc + es * v.y;
        acc.z = acc.z * sc + es * v.z;
        acc.w = acc.w * sc + es * v.w;
        Z = Z * sc + es;
        m = mn;
    }

    // Block reduction over the 16 k-slices, merging (m, Z, acc) with rescale.
    rbuf[tid] = acc;
    rm[tid]   = m;
    rz[tid]   = Z;
    __syncthreads();
#pragma unroll
    for (int s = 128; s >= 16; s >>= 1) {
        if (tid < s) {
            const float m1 = rm[tid], m2 = rm[tid + s];
            const float mn = fmaxf(m1, m2);
            const float a  = __expf(m1 - mn);
            const float b  = __expf(m2 - mn);
            float4 x = rbuf[tid];
            float4 y = rbuf[tid + s];
            x.x = x.x * a + y.x * b;
            x.y = x.y * a + y.y * b;
            x.z = x.z * a + y.z * b;
            x.w = x.w * a + y.w * b;
            rbuf[tid] = x;
            rz[tid]   = rz[tid] * a + rz[tid + s] * b;
            rm[tid]   = mn;
        }
        __syncthreads();
    }

    // tid 0..15 hold the final (m, Z, acc) for their d4. Write out row.
    if (tid < 16) {
        const float inv = 1.0f / rz[tid];
        float4 x = rbuf[tid];
        x.x *= inv; x.y *= inv; x.z *= inv; x.w *= inv;
        __stcs(reinterpret_cast<float4*>(out + (size_t)nq * DV) + tid, x);
        if (tid == 0) {
            red[0] = rm[0];
            red[1] = inv;       // rz identical across d4 (same score sequence)
        }
    }
    __syncthreads();

    // Epilogue: attn row = e^{s - m_final} / Z_final, coalesced.
    {
        const float mf  = red[0];
        const float inv = red[1];
        float* arow = attn + (size_t)nq * LK;
        __stcs(arow + tid, __expf(sa[tid] - mf) * inv);
        if (tid < LK - 256) {
            __stcs(arow + tid + 256, __expf(sa[tid + 256] - mf) * inv);
        }
    }
}

// ---------------------------------------------------------------------------
// Launch. Inputs (metadata order) = q, k, v, rel_pos, rel_pos_v.
// v and rel_pos are unused by the reference — never touched.
// Output layout: [output (NB*LQ*DV) | attn (NB*LQ*LK)] when out_size covers
// both (branch taken and passing since R3); otherwise attn -> scratch.
// ---------------------------------------------------------------------------
extern "C" void kernel_launch(void* const* d_in, const int* in_sizes, int n_in,
                              void* d_out, int out_size)
{
    const float* q   = (const float*)d_in[0];
    const float* k   = (const float*)d_in[1];
    const float* rpv = (const float*)d_in[4];
    float* out = (float*)d_out;

    const long long out_elems  = (long long)NB * LQ * DV;   // 393216
    const long long attn_elems = (long long)NB * LQ * LK;   // 2359296

    float* attn_ext = nullptr;  // null -> kernel falls back to g_attn_scratch
    if ((long long)out_size >= out_elems + attn_elems) {
        attn_ext = out + out_elems;
    }

    fused_kernel<<<NB * LQ, 256>>>(q, k, rpv, out, attn_ext);
}